// round 12
// baseline (speedup 1.0000x reference)
#include <cuda_runtime.h>
#include <cuda_fp16.h>
#include <math.h>
#include <stdint.h>

// Problem constants
#define BATCH   4096
#define HID     512
#define CARNUM  32
#define SEQLEN  33
#define TDEC    60
#define XROW    198
#define BH      (BATCH * HID)
#define MM      (HID * HID)
#define MHEAD   (TDEC * BATCH)        // 245760 rows for batched head
#define MBIG    (SEQLEN * BATCH)      // 135168 rows for hoisted encoder GEMMs

// GEMM tiling: 128x128 CTA tile, BK=64 (128B rows, SW128), 8 warps (2M x 4N)
#define BM 128
#define BN 128
#define CHUNK_K 64
#define STAGES 3
#define TILE_BYTES 16384                 // 128 rows x 128B
#define STAGE_BYTES (2 * TILE_BYTES)     // A, B
#define SMEM_REQ (1024 + STAGES * STAGE_BYTES)

#define SW128(o) ((o) ^ (((o) >> 3) & 0x70))

// ---------------- device globals ----------------------------------------------
__device__ __align__(128) __half g_S[SEQLEN * BH];        // embedded seq [t][b][h]
__device__ __align__(128) __half g_Z[SEQLEN * BH];        // hoisted pre-act partials
__device__ __align__(128) __half g_H1[(SEQLEN + 1) * BH]; // enc l1: slot0=zeros, slot t+1=h1(t)
__device__ __align__(128) __half g_He[2 * BH];            // enc l2 ping-pong
__device__ __align__(128) __half g_Hd[2 * BH];            // dec l1 ping-pong
__device__ __align__(128) __half g_H2d[(TDEC + 1) * BH];  // slot0=h2enc(32), slot k+1=h2dec(k)
__device__ __align__(128) __half g_W[9 * MM];             // fp16 weights, [n][k] layout
__device__ float g_bias[4 * HID];
__device__ float g_part[(size_t)4 * MHEAD * 2];           // head partials [nblk][row][2]

struct Ptr9 { const float* p[9]; };

// ---------------- helpers -----------------------------------------------------
__device__ __forceinline__ void cp16(unsigned dst, const void* src) {
    asm volatile("cp.async.cg.shared.global [%0], [%1], 16;" :: "r"(dst), "l"(src) : "memory");
}

__device__ __forceinline__ void ldsm4(unsigned* r, unsigned addr) {
    asm volatile("ldmatrix.sync.aligned.m8n8.x4.shared.b16 {%0,%1,%2,%3}, [%4];"
                 : "=r"(r[0]), "=r"(r[1]), "=r"(r[2]), "=r"(r[3]) : "r"(addr));
}

// fp16-accumulator HMMA (D/C are 2x f16x2 regs)
__device__ __forceinline__ void mma16816h(unsigned* d, const unsigned* a, const unsigned* b) {
    asm volatile(
        "mma.sync.aligned.m16n8k16.row.col.f16.f16.f16.f16 "
        "{%0,%1}, {%2,%3,%4,%5}, {%6,%7}, {%0,%1};"
        : "+r"(d[0]), "+r"(d[1])
        : "r"(a[0]), "r"(a[1]), "r"(a[2]), "r"(a[3]), "r"(b[0]), "r"(b[1]));
}

// ---------------- prep kernels ------------------------------------------------
__global__ void wsplit_kernel(Ptr9 s, __half* __restrict__ W) {
    int m = blockIdx.y;
    int i = blockIdx.x * blockDim.x + threadIdx.x;
    W[(size_t)m * MM + i] = __float2half(s.p[m][i]);
}

__global__ void bias_kernel(const float* __restrict__ ebih, const float* __restrict__ ebhh,
                            const float* __restrict__ dbih, const float* __restrict__ dbhh,
                            float* __restrict__ out) {
    int i = blockIdx.x * blockDim.x + threadIdx.x;
    if (i < 1024)      out[i] = ebih[i] + ebhh[i];
    else if (i < 2048) out[i] = dbih[i - 1024] + dbhh[i - 1024];
}

__global__ void zeroh_kernel(__half* __restrict__ a, int n) {
    int i = blockIdx.x * blockDim.x + threadIdx.x;
    if (i < n) a[i] = __float2half(0.f);
}

// one block per batch row; all 33 timesteps
__global__ void embed_all_kernel(const float* __restrict__ x,
                                 const float* __restrict__ Wm, const float* __restrict__ bm,
                                 const float* __restrict__ Wv, const float* __restrict__ bv,
                                 __half* __restrict__ S) {
    __shared__ float sx[XROW];
    int b = blockIdx.x, e = threadIdx.x;
    if (e < XROW) sx[e] = x[(size_t)b * XROW + e];
    __syncthreads();
    float wv[6], wm[6];
#pragma unroll
    for (int j = 0; j < 6; ++j) { wv[j] = Wv[e * 6 + j]; wm[j] = Wm[e * 6 + j]; }
    float bve = bv[e], bme = bm[e];
    for (int t = 0; t < CARNUM; ++t) {
        float s = bve;
#pragma unroll
        for (int j = 0; j < 6; ++j) s += sx[6 + 6 * t + j] * wv[j];
        S[((size_t)t * BATCH + b) * HID + e] = __float2half(tanhf(s));
    }
    {
        float s = bme;
#pragma unroll
        for (int j = 0; j < 6; ++j) s += sx[j] * wm[j];
        S[((size_t)CARNUM * BATCH + b) * HID + e] = __float2half(tanhf(s));
    }
}

// ---------------- fp16 HMMA GEMM (fp16 accum per chunk, fp32 master) ------------
// C[M, 512] = epilogue( sum_pairs A@W^T ), A row-major [m][k], W [n][k]
// act: 0 = store raw fp16 (no bias)
//      1 = tanh(acc + bias), store
//      3 = relu(acc + bias) + fused W2 head-dot -> part (no C store)
//      4 = tanh(acc + Z + bias), store
__global__ void __launch_bounds__(256, 1)
gemm_hmma(const __half* __restrict__ A1, const __half* __restrict__ A2,
          const __half* __restrict__ B1, const __half* __restrict__ B2,
          const float* __restrict__ bias, const __half* __restrict__ Z,
          __half* __restrict__ C, int act, int npairs,
          const float* __restrict__ W2, float* __restrict__ part) {
    extern __shared__ char smc[];
    unsigned smraw = (unsigned)__cvta_generic_to_shared(smc);
    unsigned sm = (smraw + 1023u) & ~1023u;

    int tid  = threadIdx.x;
    int warp = tid >> 5;
    int lane = tid & 31;
    int wm = warp >> 2;        // 0..1  (M)
    int wn = warp & 3;         // 0..3  (N)
    int li  = lane & 7;
    int grp = lane >> 3;
    int mBase = blockIdx.y * BM;
    int nBase = blockIdx.x * BN;
    int NT = npairs * (HID / CHUNK_K);      // 8 or 16

    float acc[4][4][4];
#pragma unroll
    for (int mt = 0; mt < 4; ++mt)
#pragma unroll
        for (int nt = 0; nt < 4; ++nt)
#pragma unroll
            for (int c = 0; c < 4; ++c) acc[mt][nt][c] = 0.f;

    auto prefetch = [&](int chunk) {
        int buf = chunk % STAGES;
        int pair = chunk >> 3;
        int k0 = (chunk & 7) * CHUNK_K;
        const __half* PA = pair ? A2 : A1;
        const __half* PB = pair ? B2 : B1;
        unsigned sb = sm + buf * STAGE_BYTES;
#pragma unroll
        for (int i = 0; i < 8; ++i) {
            int cid = tid + 256 * i;
            int arr = cid >> 10;               // 0 = A, 1 = B
            int r   = (cid >> 3) & 127;
            int seg = cid & 7;
            const __half* p = arr ? PB : PA;
            int rb = (arr ? nBase : mBase) + r;
            const void* src = p + (size_t)rb * HID + k0 + seg * 8;
            unsigned dst = sb + arr * TILE_BYTES + SW128(r * 128 + seg * 16);
            cp16(dst, src);
        }
        asm volatile("cp.async.commit_group;" ::: "memory");
    };

    prefetch(0);
    if (NT > 1) prefetch(1);

    for (int c = 0; c < NT; ++c) {
        if (c + 2 < NT) prefetch(c + 2);
        if (c + 2 < NT)      asm volatile("cp.async.wait_group 2;" ::: "memory");
        else if (c + 1 < NT) asm volatile("cp.async.wait_group 1;" ::: "memory");
        else                 asm volatile("cp.async.wait_group 0;" ::: "memory");
        __syncthreads();

        unsigned sb = sm + (c % STAGES) * STAGE_BYTES;
        unsigned sA = sb;
        unsigned sB = sb + TILE_BYTES;

        // fp16 chunk accumulators (zeroed per chunk; promoted to fp32 below)
        unsigned hacc[4][4][2];
#pragma unroll
        for (int mt = 0; mt < 4; ++mt)
#pragma unroll
            for (int nt = 0; nt < 4; ++nt) { hacc[mt][nt][0] = 0u; hacc[mt][nt][1] = 0u; }

#pragma unroll
        for (int kq = 0; kq < 4; ++kq) {
            unsigned a[4][4];
#pragma unroll
            for (int mt = 0; mt < 4; ++mt) {
                int r = wm * 64 + mt * 16 + ((grp & 1) << 3) + li;
                int cc = kq * 32 + ((grp & 2) << 3);
                unsigned off = (unsigned)(r * 128 + (cc ^ (li << 4)));
                ldsm4(a[mt], sA + off);
            }
            unsigned b[2][4];
#pragma unroll
            for (int nb = 0; nb < 2; ++nb) {
                int n = wn * 32 + nb * 16 + ((grp & 2) << 2) + li;
                int cc = kq * 32 + ((grp & 1) << 4);
                unsigned off = (unsigned)(n * 128 + (cc ^ (li << 4)));
                ldsm4(b[nb], sB + off);
            }
#pragma unroll
            for (int mt = 0; mt < 4; ++mt)
#pragma unroll
                for (int nt = 0; nt < 4; ++nt)
                    mma16816h(hacc[mt][nt], a[mt], &b[nt >> 1][(nt & 1) * 2]);
        }

        // promote chunk partials to fp32 masters (FMA pipe, overlaps tensor issue)
#pragma unroll
        for (int mt = 0; mt < 4; ++mt)
#pragma unroll
            for (int nt = 0; nt < 4; ++nt) {
                float2 lo = __half22float2(*reinterpret_cast<__half2*>(&hacc[mt][nt][0]));
                float2 hi = __half22float2(*reinterpret_cast<__half2*>(&hacc[mt][nt][1]));
                acc[mt][nt][0] += lo.x;
                acc[mt][nt][1] += lo.y;
                acc[mt][nt][2] += hi.x;
                acc[mt][nt][3] += hi.y;
            }
        __syncthreads();
    }

    if (act != 3) {
        // ---- epilogue: store variants ----
#pragma unroll
        for (int mt = 0; mt < 4; ++mt) {
            int r0 = mBase + wm * 64 + mt * 16 + (lane >> 2);
#pragma unroll
            for (int nt = 0; nt < 4; ++nt) {
                int n0 = nBase + wn * 32 + nt * 8 + 2 * (lane & 3);
                float b0 = 0.f, b1 = 0.f;
                if (act != 0) { b0 = bias[n0]; b1 = bias[n0 + 1]; }
#pragma unroll
                for (int half_ = 0; half_ < 2; ++half_) {
                    int r = r0 + half_ * 8;
                    float v0 = acc[mt][nt][half_ * 2 + 0] + b0;
                    float v1 = acc[mt][nt][half_ * 2 + 1] + b1;
                    if (act == 4) {
                        __half2 z2 = *reinterpret_cast<const __half2*>(&Z[(size_t)r * HID + n0]);
                        v0 += __half2float(z2.x);
                        v1 += __half2float(z2.y);
                    }
                    if (act == 1 || act == 4) { v0 = tanhf(v0); v1 = tanhf(v1); }
                    __half2 hv; hv.x = __float2half(v0); hv.y = __float2half(v1);
                    *reinterpret_cast<__half2*>(&C[(size_t)r * HID + n0]) = hv;
                }
            }
        }
    } else {
        // ---- epilogue: bias + relu + fused head-dot (no C store) ----
        float p0[8], p1[8];
#pragma unroll
        for (int s2 = 0; s2 < 8; ++s2) { p0[s2] = 0.f; p1[s2] = 0.f; }
#pragma unroll
        for (int nt = 0; nt < 4; ++nt) {
            int n0 = nBase + wn * 32 + nt * 8 + 2 * (lane & 3);
            float b0 = bias[n0], b1 = bias[n0 + 1];
            float w00 = W2[n0], w01 = W2[n0 + 1];
            float w10 = W2[HID + n0], w11 = W2[HID + n0 + 1];
#pragma unroll
            for (int mt = 0; mt < 4; ++mt)
#pragma unroll
                for (int half_ = 0; half_ < 2; ++half_) {
                    float v0 = fmaxf(acc[mt][nt][half_ * 2 + 0] + b0, 0.f);
                    float v1 = fmaxf(acc[mt][nt][half_ * 2 + 1] + b1, 0.f);
                    int s2 = mt * 2 + half_;
                    p0[s2] += v0 * w00 + v1 * w01;
                    p1[s2] += v0 * w10 + v1 * w11;
                }
        }
#pragma unroll
        for (int s2 = 0; s2 < 8; ++s2) {
            p0[s2] += __shfl_xor_sync(0xffffffffu, p0[s2], 1);
            p0[s2] += __shfl_xor_sync(0xffffffffu, p0[s2], 2);
            p1[s2] += __shfl_xor_sync(0xffffffffu, p1[s2], 1);
            p1[s2] += __shfl_xor_sync(0xffffffffu, p1[s2], 2);
        }
        float* red = (float*)smc;             // [128 rows][2 outs][4 wn] = 4 KB
        if ((lane & 3) == 0) {
#pragma unroll
            for (int mt = 0; mt < 4; ++mt)
#pragma unroll
                for (int half_ = 0; half_ < 2; ++half_) {
                    int rl = wm * 64 + mt * 16 + (lane >> 2) + half_ * 8;
                    int s2 = mt * 2 + half_;
                    red[(rl * 2 + 0) * 4 + wn] = p0[s2];
                    red[(rl * 2 + 1) * 4 + wn] = p1[s2];
                }
        }
        __syncthreads();
        {
            float s = red[tid * 4 + 0] + red[tid * 4 + 1] + red[tid * 4 + 2] + red[tid * 4 + 3];
            part[((size_t)blockIdx.x * MHEAD + mBase + (tid >> 1)) * 2 + (tid & 1)] = s;
        }
    }
}

// out[b][t][o] = tanh(sum_4 part + b2[o]); row r = t*BATCH + b
__global__ void finalize_kernel(const float* __restrict__ part,
                                const float* __restrict__ b2, float* __restrict__ out) {
    int idx = blockIdx.x * blockDim.x + threadIdx.x;
    if (idx >= MHEAD * 2) return;
    int o = idx & 1;
    int r = idx >> 1;
    int b = r & (BATCH - 1);
    int t = r >> 12;
    float s = part[((size_t)0 * MHEAD + r) * 2 + o]
            + part[((size_t)1 * MHEAD + r) * 2 + o]
            + part[((size_t)2 * MHEAD + r) * 2 + o]
            + part[((size_t)3 * MHEAD + r) * 2 + o];
    out[((size_t)b * TDEC + t) * 2 + o] = tanhf(s + b2[o]);
}

// ---------------- launch ------------------------------------------------------
extern "C" void kernel_launch(void* const* d_in, const int* in_sizes, int n_in,
                              void* d_out, int out_size) {
    (void)in_sizes; (void)n_in; (void)out_size;
    const float* x      = (const float*)d_in[0];
    const float* emW    = (const float*)d_in[1];
    const float* emb    = (const float*)d_in[2];
    const float* evW    = (const float*)d_in[3];
    const float* evb    = (const float*)d_in[4];
    const float* encWih = (const float*)d_in[5];
    const float* encWhh = (const float*)d_in[6];
    const float* encbih = (const float*)d_in[7];
    const float* encbhh = (const float*)d_in[8];
    const float* decWih = (const float*)d_in[9];
    const float* decWhh = (const float*)d_in[10];
    const float* decbih = (const float*)d_in[11];
    const float* decbhh = (const float*)d_in[12];
    const float* headW1 = (const float*)d_in[13];
    const float* headb1 = (const float*)d_in[14];
    const float* headW2 = (const float*)d_in[15];
    const float* headb2 = (const float*)d_in[16];
    float* out = (float*)d_out;

    __half *S, *Zb, *H1, *He, *Hd, *H2d, *W;
    float *bias, *part;
    cudaGetSymbolAddress((void**)&S,   g_S);
    cudaGetSymbolAddress((void**)&Zb,  g_Z);
    cudaGetSymbolAddress((void**)&H1,  g_H1);
    cudaGetSymbolAddress((void**)&He,  g_He);
    cudaGetSymbolAddress((void**)&Hd,  g_Hd);
    cudaGetSymbolAddress((void**)&H2d, g_H2d);
    cudaGetSymbolAddress((void**)&W,   g_W);
    cudaGetSymbolAddress((void**)&bias, g_bias);
    cudaGetSymbolAddress((void**)&part, g_part);

    cudaFuncSetAttribute(gemm_hmma, cudaFuncAttributeMaxDynamicSharedMemorySize, SMEM_REQ);

    Ptr9 src;
    src.p[0] = encWih;        src.p[1] = encWhh;
    src.p[2] = encWih + MM;   src.p[3] = encWhh + MM;
    src.p[4] = decWih;        src.p[5] = decWhh;
    src.p[6] = decWih + MM;   src.p[7] = decWhh + MM;
    src.p[8] = headW1;

    wsplit_kernel<<<dim3(MM / 256, 9), 256>>>(src, W);
    bias_kernel<<<8, 256>>>(encbih, encbhh, decbih, decbhh, bias);
    zeroh_kernel<<<(BH + 255) / 256, 256>>>(H1, BH);     // H1 slot 0 = zeros
    embed_all_kernel<<<BATCH, HID>>>(x, emW, emb, evW, evb, S);

    const __half* ZN = nullptr;
    const float* FN = nullptr;
    __half* CN = nullptr;
    dim3 gSerial(4, 32);

    // ===== encoder =====
    // Z1 = S @ Wih0^T  (hoisted, 135K rows, full-chip)
    gemm_hmma<<<dim3(4, MBIG / BM), 256, SMEM_REQ>>>(
        S, ZN, W + 0 * MM, ZN, FN, ZN, Zb, 0, 1, FN, (float*)nullptr);
    // serial l1 chain: h1(t) = tanh(h1(t-1)@Whh0^T + Z1[t] + b0)
    for (int t = 0; t < SEQLEN; ++t) {
        gemm_hmma<<<gSerial, 256, SMEM_REQ>>>(
            H1 + (size_t)t * BH, ZN, W + 1 * MM, ZN,
            bias + 0 * HID, Zb + (size_t)t * BH,
            H1 + (size_t)(t + 1) * BH, 4, 1, FN, (float*)nullptr);
    }
    // Z2 = H1[1..33] @ Wih1^T  (hoisted)
    gemm_hmma<<<dim3(4, MBIG / BM), 256, SMEM_REQ>>>(
        H1 + BH, ZN, W + 2 * MM, ZN, FN, ZN, Zb, 0, 1, FN, (float*)nullptr);
    // serial l2 chain: h2(t) = tanh(h2(t-1)@Whh1^T + Z2[t] + b1); h2(32) -> H2d slot 0
    for (int t = 0; t < SEQLEN; ++t) {
        const __half* Aprev = (t == 0) ? H1 /*zeros*/ : He + (size_t)((t - 1) & 1) * BH;
        __half* dst = (t == SEQLEN - 1) ? H2d : He + (size_t)(t & 1) * BH;
        gemm_hmma<<<gSerial, 256, SMEM_REQ>>>(
            Aprev, ZN, W + 3 * MM, ZN,
            bias + 1 * HID, Zb + (size_t)t * BH,
            dst, 4, 1, FN, (float*)nullptr);
    }

    // ===== decoder =====
    for (int k = 0; k < TDEC; ++k) {
        const __half* h1prev = (k == 0) ? H1 + (size_t)SEQLEN * BH
                                        : Hd + (size_t)((k - 1) & 1) * BH;
        __half* h1cur = Hd + (size_t)(k & 1) * BH;
        // l1: tanh(top(k-1)@Wih0d^T + h1prev@Whh0d^T + b2)
        gemm_hmma<<<gSerial, 256, SMEM_REQ>>>(
            H2d + (size_t)k * BH, h1prev, W + 4 * MM, W + 5 * MM,
            bias + 2 * HID, ZN, h1cur, 1, 2, FN, (float*)nullptr);
        // l2: tanh(h1cur@Wih1d^T + h2(k-1)@Whh1d^T + b3) -> H2d slot k+1
        gemm_hmma<<<gSerial, 256, SMEM_REQ>>>(
            h1cur, H2d + (size_t)k * BH, W + 6 * MM, W + 7 * MM,
            bias + 3 * HID, ZN, H2d + (size_t)(k + 1) * BH, 1, 2, FN, (float*)nullptr);
    }

    // ===== batched head: relu(H2d[1..60]@W1^T + b1) . W2 -> part =====
    gemm_hmma<<<dim3(4, MHEAD / BM), 256, SMEM_REQ>>>(
        H2d + BH, ZN, W + 8 * MM, ZN,
        headb1, ZN, CN, 3, 1, headW2, part);

    finalize_kernel<<<(MHEAD * 2 + 255) / 256, 256>>>(part, headb2, out);
}

// round 13
// speedup vs baseline: 1.1536x; 1.1536x over previous
#include <cuda_runtime.h>
#include <cuda_fp16.h>
#include <math.h>
#include <stdint.h>

// Problem constants
#define BATCH   4096
#define HID     512
#define CARNUM  32
#define SEQLEN  33
#define TDEC    60
#define XROW    198
#define BH      (BATCH * HID)
#define MM      (HID * HID)
#define MHEAD   (TDEC * BATCH)

// GEMM tiling: 128x128 CTA tile, BK=64 (128B rows, SW128), 8 warps (2M x 4N)
#define BM 128
#define BN 128
#define CHUNK_K 64
#define STAGES 3
#define TILE_BYTES 16384
#define STAGE_BYTES (2 * TILE_BYTES)
#define SMEM_REQ (1024 + STAGES * STAGE_BYTES)

#define SW128(o) ((o) ^ (((o) >> 3) & 0x70))

// ---------------- device globals ----------------------------------------------
__device__ __align__(128) __half g_S[SEQLEN * BH];
__device__ __align__(128) __half g_Z[SEQLEN * BH];
__device__ __align__(128) __half g_H1[(SEQLEN + 1) * BH];
__device__ __align__(128) __half g_He[2 * BH];
__device__ __align__(128) __half g_Hd[2 * BH];
__device__ __align__(128) __half g_H2d[(TDEC + 1) * BH];
__device__ __align__(128) __half g_W[9 * MM];
__device__ float g_bias[4 * HID];
__device__ float g_part[(size_t)4 * MHEAD * 2];

struct Ptr9 { const float* p[9]; };

// ---------------- helpers -----------------------------------------------------
__device__ __forceinline__ void cp16(unsigned dst, const void* src) {
    asm volatile("cp.async.cg.shared.global [%0], [%1], 16;" :: "r"(dst), "l"(src) : "memory");
}

__device__ __forceinline__ void ldsm4(unsigned* r, unsigned addr) {
    asm volatile("ldmatrix.sync.aligned.m8n8.x4.shared.b16 {%0,%1,%2,%3}, [%4];"
                 : "=r"(r[0]), "=r"(r[1]), "=r"(r[2]), "=r"(r[3]) : "r"(addr));
}

__device__ __forceinline__ void mma16816(float* c, const unsigned* a, const unsigned* b) {
    asm volatile(
        "mma.sync.aligned.m16n8k16.row.col.f32.f16.f16.f32 "
        "{%0,%1,%2,%3}, {%4,%5,%6,%7}, {%8,%9}, {%0,%1,%2,%3};"
        : "+f"(c[0]), "+f"(c[1]), "+f"(c[2]), "+f"(c[3])
        : "r"(a[0]), "r"(a[1]), "r"(a[2]), "r"(a[3]), "r"(b[0]), "r"(b[1]));
}

// ---------------- prep kernels ------------------------------------------------
__global__ void wsplit_kernel(Ptr9 s, __half* __restrict__ W) {
    int m = blockIdx.y;
    int i = blockIdx.x * blockDim.x + threadIdx.x;
    W[(size_t)m * MM + i] = __float2half(s.p[m][i]);
}

__global__ void bias_kernel(const float* __restrict__ ebih, const float* __restrict__ ebhh,
                            const float* __restrict__ dbih, const float* __restrict__ dbhh,
                            float* __restrict__ out) {
    int i = blockIdx.x * blockDim.x + threadIdx.x;
    if (i < 1024)      out[i] = ebih[i] + ebhh[i];
    else if (i < 2048) out[i] = dbih[i - 1024] + dbhh[i - 1024];
}

__global__ void zeroh_kernel(__half* __restrict__ a, int n) {
    int i = blockIdx.x * blockDim.x + threadIdx.x;
    if (i < n) a[i] = __float2half(0.f);
}

// one block per batch row; all 33 timesteps
__global__ void embed_all_kernel(const float* __restrict__ x,
                                 const float* __restrict__ Wm, const float* __restrict__ bm,
                                 const float* __restrict__ Wv, const float* __restrict__ bv,
                                 __half* __restrict__ S) {
    __shared__ float sx[XROW];
    int b = blockIdx.x, e = threadIdx.x;
    if (e < XROW) sx[e] = x[(size_t)b * XROW + e];
    __syncthreads();
    float wv[6], wm[6];
#pragma unroll
    for (int j = 0; j < 6; ++j) { wv[j] = Wv[e * 6 + j]; wm[j] = Wm[e * 6 + j]; }
    float bve = bv[e], bme = bm[e];
    for (int t = 0; t < CARNUM; ++t) {
        float s = bve;
#pragma unroll
        for (int j = 0; j < 6; ++j) s += sx[6 + 6 * t + j] * wv[j];
        S[((size_t)t * BATCH + b) * HID + e] = __float2half(tanhf(s));
    }
    {
        float s = bme;
#pragma unroll
        for (int j = 0; j < 6; ++j) s += sx[j] * wm[j];
        S[((size_t)CARNUM * BATCH + b) * HID + e] = __float2half(tanhf(s));
    }
}

// ---------------- fp16 HMMA GEMM ------------------------------------------------
// C[M, 512] = epilogue( sum_pairs A@W^T ), A row-major [m][k], W [n][k]
// act: 0 = store raw fp16 (no bias)
//      1 = tanh(acc + bias), store
//      3 = relu(acc + bias) + fused W2 head-dot -> part (no C store)
//      4 = tanh(acc + Z + bias), store
__global__ void __launch_bounds__(256, 1)
gemm_hmma(const __half* __restrict__ A1, const __half* __restrict__ A2,
          const __half* __restrict__ B1, const __half* __restrict__ B2,
          const float* __restrict__ bias, const __half* __restrict__ Z,
          __half* __restrict__ C, int act, int npairs,
          const float* __restrict__ W2, float* __restrict__ part) {
    extern __shared__ char smc[];
    unsigned smraw = (unsigned)__cvta_generic_to_shared(smc);
    unsigned sm = (smraw + 1023u) & ~1023u;

    int tid  = threadIdx.x;
    int warp = tid >> 5;
    int lane = tid & 31;
    int wm = warp >> 2;
    int wn = warp & 3;
    int li  = lane & 7;
    int grp = lane >> 3;
    int mBase = blockIdx.y * BM;
    int nBase = blockIdx.x * BN;
    int NT = npairs * (HID / CHUNK_K);

    float acc[4][4][4];
#pragma unroll
    for (int mt = 0; mt < 4; ++mt)
#pragma unroll
        for (int nt = 0; nt < 4; ++nt)
#pragma unroll
            for (int c = 0; c < 4; ++c) acc[mt][nt][c] = 0.f;

    auto prefetch = [&](int chunk) {
        int buf = chunk % STAGES;
        int pair = chunk >> 3;
        int k0 = (chunk & 7) * CHUNK_K;
        const __half* PA = pair ? A2 : A1;
        const __half* PB = pair ? B2 : B1;
        unsigned sb = sm + buf * STAGE_BYTES;
#pragma unroll
        for (int i = 0; i < 8; ++i) {
            int cid = tid + 256 * i;
            int arr = cid >> 10;
            int r   = (cid >> 3) & 127;
            int seg = cid & 7;
            const __half* p = arr ? PB : PA;
            int rb = (arr ? nBase : mBase) + r;
            const void* src = p + (size_t)rb * HID + k0 + seg * 8;
            unsigned dst = sb + arr * TILE_BYTES + SW128(r * 128 + seg * 16);
            cp16(dst, src);
        }
        asm volatile("cp.async.commit_group;" ::: "memory");
    };

    prefetch(0);
    if (NT > 1) prefetch(1);

    for (int c = 0; c < NT; ++c) {
        if (c + 2 < NT) prefetch(c + 2);
        if (c + 2 < NT)      asm volatile("cp.async.wait_group 2;" ::: "memory");
        else if (c + 1 < NT) asm volatile("cp.async.wait_group 1;" ::: "memory");
        else                 asm volatile("cp.async.wait_group 0;" ::: "memory");
        __syncthreads();

        unsigned sb = sm + (c % STAGES) * STAGE_BYTES;
        unsigned sA = sb;
        unsigned sB = sb + TILE_BYTES;

#pragma unroll
        for (int kq = 0; kq < 4; ++kq) {
            unsigned a[4][4];
#pragma unroll
            for (int mt = 0; mt < 4; ++mt) {
                int r = wm * 64 + mt * 16 + ((grp & 1) << 3) + li;
                int cc = kq * 32 + ((grp & 2) << 3);
                unsigned off = (unsigned)(r * 128 + (cc ^ (li << 4)));
                ldsm4(a[mt], sA + off);
            }
            unsigned b[2][4];
#pragma unroll
            for (int nb = 0; nb < 2; ++nb) {
                int n = wn * 32 + nb * 16 + ((grp & 2) << 2) + li;
                int cc = kq * 32 + ((grp & 1) << 4);
                unsigned off = (unsigned)(n * 128 + (cc ^ (li << 4)));
                ldsm4(b[nb], sB + off);
            }
#pragma unroll
            for (int mt = 0; mt < 4; ++mt)
#pragma unroll
                for (int nt = 0; nt < 4; ++nt)
                    mma16816(acc[mt][nt], a[mt], &b[nt >> 1][(nt & 1) * 2]);
        }
        __syncthreads();
    }

    if (act != 3) {
#pragma unroll
        for (int mt = 0; mt < 4; ++mt) {
            int r0 = mBase + wm * 64 + mt * 16 + (lane >> 2);
#pragma unroll
            for (int nt = 0; nt < 4; ++nt) {
                int n0 = nBase + wn * 32 + nt * 8 + 2 * (lane & 3);
                float b0 = 0.f, b1 = 0.f;
                if (act != 0) { b0 = bias[n0]; b1 = bias[n0 + 1]; }
#pragma unroll
                for (int half_ = 0; half_ < 2; ++half_) {
                    int r = r0 + half_ * 8;
                    float v0 = acc[mt][nt][half_ * 2 + 0] + b0;
                    float v1 = acc[mt][nt][half_ * 2 + 1] + b1;
                    if (act == 4) {
                        __half2 z2 = *reinterpret_cast<const __half2*>(&Z[(size_t)r * HID + n0]);
                        v0 += __half2float(z2.x);
                        v1 += __half2float(z2.y);
                    }
                    if (act == 1 || act == 4) { v0 = tanhf(v0); v1 = tanhf(v1); }
                    __half2 hv; hv.x = __float2half(v0); hv.y = __float2half(v1);
                    *reinterpret_cast<__half2*>(&C[(size_t)r * HID + n0]) = hv;
                }
            }
        }
    } else {
        float p0[8], p1[8];
#pragma unroll
        for (int s2i = 0; s2i < 8; ++s2i) { p0[s2i] = 0.f; p1[s2i] = 0.f; }
#pragma unroll
        for (int nt = 0; nt < 4; ++nt) {
            int n0 = nBase + wn * 32 + nt * 8 + 2 * (lane & 3);
            float b0 = bias[n0], b1 = bias[n0 + 1];
            float w00 = W2[n0], w01 = W2[n0 + 1];
            float w10 = W2[HID + n0], w11 = W2[HID + n0 + 1];
#pragma unroll
            for (int mt = 0; mt < 4; ++mt)
#pragma unroll
                for (int half_ = 0; half_ < 2; ++half_) {
                    float v0 = fmaxf(acc[mt][nt][half_ * 2 + 0] + b0, 0.f);
                    float v1 = fmaxf(acc[mt][nt][half_ * 2 + 1] + b1, 0.f);
                    int s2i = mt * 2 + half_;
                    p0[s2i] += v0 * w00 + v1 * w01;
                    p1[s2i] += v0 * w10 + v1 * w11;
                }
        }
#pragma unroll
        for (int s2i = 0; s2i < 8; ++s2i) {
            p0[s2i] += __shfl_xor_sync(0xffffffffu, p0[s2i], 1);
            p0[s2i] += __shfl_xor_sync(0xffffffffu, p0[s2i], 2);
            p1[s2i] += __shfl_xor_sync(0xffffffffu, p1[s2i], 1);
            p1[s2i] += __shfl_xor_sync(0xffffffffu, p1[s2i], 2);
        }
        float* red = (float*)smc;
        if ((lane & 3) == 0) {
#pragma unroll
            for (int mt = 0; mt < 4; ++mt)
#pragma unroll
                for (int half_ = 0; half_ < 2; ++half_) {
                    int rl = wm * 64 + mt * 16 + (lane >> 2) + half_ * 8;
                    int s2i = mt * 2 + half_;
                    red[(rl * 2 + 0) * 4 + wn] = p0[s2i];
                    red[(rl * 2 + 1) * 4 + wn] = p1[s2i];
                }
        }
        __syncthreads();
        {
            float s = red[tid * 4 + 0] + red[tid * 4 + 1] + red[tid * 4 + 2] + red[tid * 4 + 3];
            part[((size_t)blockIdx.x * MHEAD + mBase + (tid >> 1)) * 2 + (tid & 1)] = s;
        }
    }
}

// out[b][t][o] = tanh(sum_4 part + b2[o]); row r = t*BATCH + b
__global__ void finalize_kernel(const float* __restrict__ part,
                                const float* __restrict__ b2, float* __restrict__ out) {
    int idx = blockIdx.x * blockDim.x + threadIdx.x;
    if (idx >= MHEAD * 2) return;
    int o = idx & 1;
    int r = idx >> 1;
    int b = r & (BATCH - 1);
    int t = r >> 12;
    float s = part[((size_t)0 * MHEAD + r) * 2 + o]
            + part[((size_t)1 * MHEAD + r) * 2 + o]
            + part[((size_t)2 * MHEAD + r) * 2 + o]
            + part[((size_t)3 * MHEAD + r) * 2 + o];
    out[((size_t)b * TDEC + t) * 2 + o] = tanhf(s + b2[o]);
}

// ---------------- static stream/event resources --------------------------------
static cudaStream_t g_s2 = nullptr;
static cudaEvent_t g_evEmb;
static cudaEvent_t g_evZ1[SEQLEN];   // Z1 part t ready (s2)
static cudaEvent_t g_evE[SEQLEN];    // enc l1 step t done (main)
static cudaEvent_t g_evZ2[SEQLEN];   // Z2 part t ready (s2)
static cudaEvent_t g_evD[TDEC];      // dec l2 step k done (main)
static cudaEvent_t g_evHead;         // all head parts done (s2)

static void ensure_resources() {
    if (g_s2) return;
    cudaStreamCreateWithFlags(&g_s2, cudaStreamNonBlocking);
    cudaEventCreateWithFlags(&g_evEmb, cudaEventDisableTiming);
    for (int i = 0; i < SEQLEN; ++i) {
        cudaEventCreateWithFlags(&g_evZ1[i], cudaEventDisableTiming);
        cudaEventCreateWithFlags(&g_evE[i],  cudaEventDisableTiming);
        cudaEventCreateWithFlags(&g_evZ2[i], cudaEventDisableTiming);
    }
    for (int i = 0; i < TDEC; ++i)
        cudaEventCreateWithFlags(&g_evD[i], cudaEventDisableTiming);
    cudaEventCreateWithFlags(&g_evHead, cudaEventDisableTiming);
}

// ---------------- launch ------------------------------------------------------
extern "C" void kernel_launch(void* const* d_in, const int* in_sizes, int n_in,
                              void* d_out, int out_size) {
    (void)in_sizes; (void)n_in; (void)out_size;
    const float* x      = (const float*)d_in[0];
    const float* emW    = (const float*)d_in[1];
    const float* emb    = (const float*)d_in[2];
    const float* evW    = (const float*)d_in[3];
    const float* evb    = (const float*)d_in[4];
    const float* encWih = (const float*)d_in[5];
    const float* encWhh = (const float*)d_in[6];
    const float* encbih = (const float*)d_in[7];
    const float* encbhh = (const float*)d_in[8];
    const float* decWih = (const float*)d_in[9];
    const float* decWhh = (const float*)d_in[10];
    const float* decbih = (const float*)d_in[11];
    const float* decbhh = (const float*)d_in[12];
    const float* headW1 = (const float*)d_in[13];
    const float* headb1 = (const float*)d_in[14];
    const float* headW2 = (const float*)d_in[15];
    const float* headb2 = (const float*)d_in[16];
    float* out = (float*)d_out;

    ensure_resources();

    __half *S, *Zb, *H1, *He, *Hd, *H2d, *W;
    float *bias, *part;
    cudaGetSymbolAddress((void**)&S,   g_S);
    cudaGetSymbolAddress((void**)&Zb,  g_Z);
    cudaGetSymbolAddress((void**)&H1,  g_H1);
    cudaGetSymbolAddress((void**)&He,  g_He);
    cudaGetSymbolAddress((void**)&Hd,  g_Hd);
    cudaGetSymbolAddress((void**)&H2d, g_H2d);
    cudaGetSymbolAddress((void**)&W,   g_W);
    cudaGetSymbolAddress((void**)&bias, g_bias);
    cudaGetSymbolAddress((void**)&part, g_part);

    cudaFuncSetAttribute(gemm_hmma, cudaFuncAttributeMaxDynamicSharedMemorySize, SMEM_REQ);

    Ptr9 src;
    src.p[0] = encWih;        src.p[1] = encWhh;
    src.p[2] = encWih + MM;   src.p[3] = encWhh + MM;
    src.p[4] = decWih;        src.p[5] = decWhh;
    src.p[6] = decWih + MM;   src.p[7] = decWhh + MM;
    src.p[8] = headW1;

    wsplit_kernel<<<dim3(MM / 256, 9), 256>>>(src, W);
    bias_kernel<<<8, 256>>>(encbih, encbhh, decbih, decbhh, bias);
    zeroh_kernel<<<(BH + 255) / 256, 256>>>(H1, BH);
    embed_all_kernel<<<BATCH, HID>>>(x, emW, emb, evW, evb, S);
    cudaEventRecord(g_evEmb, 0);

    const __half* ZN = nullptr;
    const float* FN = nullptr;
    __half* CN = nullptr;
    dim3 gSerial(4, 32);

    // ===== s2: Z1 parts 1..32 (depend on embed only) =====
    cudaStreamWaitEvent(g_s2, g_evEmb, 0);
    for (int t = 1; t < SEQLEN; ++t) {
        gemm_hmma<<<gSerial, 256, SMEM_REQ, g_s2>>>(
            S + (size_t)t * BH, ZN, W + 0 * MM, ZN, FN, ZN,
            Zb + (size_t)t * BH, 0, 1, FN, (float*)nullptr);
        cudaEventRecord(g_evZ1[t], g_s2);
    }

    // ===== main: Z1 part 0, then serial l1 chain =====
    gemm_hmma<<<gSerial, 256, SMEM_REQ>>>(
        S, ZN, W + 0 * MM, ZN, FN, ZN, Zb, 0, 1, FN, (float*)nullptr);
    for (int t = 0; t < SEQLEN; ++t) {
        if (t >= 1) cudaStreamWaitEvent(0, g_evZ1[t], 0);
        gemm_hmma<<<gSerial, 256, SMEM_REQ>>>(
            H1 + (size_t)t * BH, ZN, W + 1 * MM, ZN,
            bias + 0 * HID, Zb + (size_t)t * BH,
            H1 + (size_t)(t + 1) * BH, 4, 1, FN, (float*)nullptr);
        cudaEventRecord(g_evE[t], 0);
    }

    // ===== s2: Z2 parts (each needs l1 step t done; overwrites Zb slot t) =====
    for (int t = 0; t < SEQLEN; ++t) {
        cudaStreamWaitEvent(g_s2, g_evE[t], 0);
        gemm_hmma<<<gSerial, 256, SMEM_REQ, g_s2>>>(
            H1 + (size_t)(t + 1) * BH, ZN, W + 2 * MM, ZN, FN, ZN,
            Zb + (size_t)t * BH, 0, 1, FN, (float*)nullptr);
        cudaEventRecord(g_evZ2[t], g_s2);
    }

    // ===== main: serial l2 chain =====
    for (int t = 0; t < SEQLEN; ++t) {
        cudaStreamWaitEvent(0, g_evZ2[t], 0);
        const __half* Aprev = (t == 0) ? H1 /*zeros*/ : He + (size_t)((t - 1) & 1) * BH;
        __half* dst = (t == SEQLEN - 1) ? H2d : He + (size_t)(t & 1) * BH;
        gemm_hmma<<<gSerial, 256, SMEM_REQ>>>(
            Aprev, ZN, W + 3 * MM, ZN,
            bias + 1 * HID, Zb + (size_t)t * BH,
            dst, 4, 1, FN, (float*)nullptr);
    }

    // ===== main: decoder; s2: per-k head parts overlapped =====
    for (int k = 0; k < TDEC; ++k) {
        const __half* h1prev = (k == 0) ? H1 + (size_t)SEQLEN * BH
                                        : Hd + (size_t)((k - 1) & 1) * BH;
        __half* h1cur = Hd + (size_t)(k & 1) * BH;
        gemm_hmma<<<gSerial, 256, SMEM_REQ>>>(
            H2d + (size_t)k * BH, h1prev, W + 4 * MM, W + 5 * MM,
            bias + 2 * HID, ZN, h1cur, 1, 2, FN, (float*)nullptr);
        gemm_hmma<<<gSerial, 256, SMEM_REQ>>>(
            h1cur, H2d + (size_t)k * BH, W + 6 * MM, W + 7 * MM,
            bias + 3 * HID, ZN, H2d + (size_t)(k + 1) * BH, 1, 2, FN, (float*)nullptr);
        cudaEventRecord(g_evD[k], 0);

        cudaStreamWaitEvent(g_s2, g_evD[k], 0);
        gemm_hmma<<<gSerial, 256, SMEM_REQ, g_s2>>>(
            H2d + (size_t)(k + 1) * BH, ZN, W + 8 * MM, ZN,
            headb1, ZN, CN, 3, 1, headW2,
            part + (size_t)k * BATCH * 2);
    }
    cudaEventRecord(g_evHead, g_s2);

    // ===== join + finalize =====
    cudaStreamWaitEvent(0, g_evHead, 0);
    finalize_kernel<<<(MHEAD * 2 + 255) / 256, 256>>>(part, headb2, out);
}

// round 16
// speedup vs baseline: 1.1553x; 1.0015x over previous
#include <cuda_runtime.h>
#include <cuda_fp16.h>
#include <math.h>
#include <stdint.h>

// Problem constants
#define BATCH   4096
#define HID     512
#define CARNUM  32
#define SEQLEN  33
#define TDEC    60
#define XROW    198
#define BH      (BATCH * HID)
#define MM      (HID * HID)
#define MHEAD   (TDEC * BATCH)

// GEMM tiling: 128x128 CTA tile, BK=64 (128B rows, SW128), 8 warps (2M x 4N)
#define BM 128
#define BN 128
#define CHUNK_K 64
#define STAGES 3
#define TILE_BYTES 16384
#define STAGE_BYTES (2 * TILE_BYTES)
#define SMEM_REQ (1024 + STAGES * STAGE_BYTES)

#define SW128(o) ((o) ^ (((o) >> 3) & 0x70))

// ---------------- device globals ----------------------------------------------
__device__ __align__(128) __half g_S[SEQLEN * BH];
__device__ __align__(128) __half g_Z[SEQLEN * BH];
__device__ __align__(128) __half g_H1[(SEQLEN + 1) * BH];
__device__ __align__(128) __half g_He[2 * BH];
__device__ __align__(128) __half g_Hd[2 * BH];
__device__ __align__(128) __half g_H2d[(TDEC + 1) * BH];
__device__ __align__(128) __half g_W[9 * MM];
__device__ float g_bias[4 * HID];
__device__ float g_part[(size_t)4 * MHEAD * 2];

struct Ptr9 { const float* p[9]; };

// ---------------- helpers -----------------------------------------------------
__device__ __forceinline__ void cp16(unsigned dst, const void* src) {
    asm volatile("cp.async.cg.shared.global [%0], [%1], 16;" :: "r"(dst), "l"(src) : "memory");
}

__device__ __forceinline__ void ldsm4(unsigned* r, unsigned addr) {
    asm volatile("ldmatrix.sync.aligned.m8n8.x4.shared.b16 {%0,%1,%2,%3}, [%4];"
                 : "=r"(r[0]), "=r"(r[1]), "=r"(r[2]), "=r"(r[3]) : "r"(addr));
}

__device__ __forceinline__ void mma16816(float* c, const unsigned* a, const unsigned* b) {
    asm volatile(
        "mma.sync.aligned.m16n8k16.row.col.f32.f16.f16.f32 "
        "{%0,%1,%2,%3}, {%4,%5,%6,%7}, {%8,%9}, {%0,%1,%2,%3};"
        : "+f"(c[0]), "+f"(c[1]), "+f"(c[2]), "+f"(c[3])
        : "r"(a[0]), "r"(a[1]), "r"(a[2]), "r"(a[3]), "r"(b[0]), "r"(b[1]));
}

// ---------------- prep kernels ------------------------------------------------
__global__ void wsplit_kernel(Ptr9 s, __half* __restrict__ W) {
    int m = blockIdx.y;
    int i = blockIdx.x * blockDim.x + threadIdx.x;
    W[(size_t)m * MM + i] = __float2half(s.p[m][i]);
}

__global__ void bias_kernel(const float* __restrict__ ebih, const float* __restrict__ ebhh,
                            const float* __restrict__ dbih, const float* __restrict__ dbhh,
                            float* __restrict__ out) {
    int i = blockIdx.x * blockDim.x + threadIdx.x;
    if (i < 1024)      out[i] = ebih[i] + ebhh[i];
    else if (i < 2048) out[i] = dbih[i - 1024] + dbhh[i - 1024];
}

__global__ void zeroh_kernel(__half* __restrict__ a, int n) {
    int i = blockIdx.x * blockDim.x + threadIdx.x;
    if (i < n) a[i] = __float2half(0.f);
}

// one block per batch row; 256 threads, 2 hidden units each; half2 stores
__global__ void embed_all_kernel(const float* __restrict__ x,
                                 const float* __restrict__ Wm, const float* __restrict__ bm,
                                 const float* __restrict__ Wv, const float* __restrict__ bv,
                                 __half* __restrict__ S) {
    __shared__ float sx[XROW];
    int b = blockIdx.x, tid = threadIdx.x;
    if (tid < XROW) sx[tid] = x[(size_t)b * XROW + tid];
    __syncthreads();
    int e0 = tid * 2;
    float wv0[6], wv1[6], wm0[6], wm1[6];
#pragma unroll
    for (int j = 0; j < 6; ++j) {
        wv0[j] = Wv[e0 * 6 + j];       wv1[j] = Wv[(e0 + 1) * 6 + j];
        wm0[j] = Wm[e0 * 6 + j];       wm1[j] = Wm[(e0 + 1) * 6 + j];
    }
    float bv0 = bv[e0], bv1 = bv[e0 + 1];
    float bm0 = bm[e0], bm1 = bm[e0 + 1];
    size_t base = (size_t)b * HID + e0;
    for (int t = 0; t < CARNUM; ++t) {
        float s0 = bv0, s1 = bv1;
#pragma unroll
        for (int j = 0; j < 6; ++j) {
            float xv = sx[6 + 6 * t + j];
            s0 += xv * wv0[j];
            s1 += xv * wv1[j];
        }
        __half2 h; h.x = __float2half(tanhf(s0)); h.y = __float2half(tanhf(s1));
        *reinterpret_cast<__half2*>(&S[(size_t)t * BH + base]) = h;
    }
    {
        float s0 = bm0, s1 = bm1;
#pragma unroll
        for (int j = 0; j < 6; ++j) {
            float xv = sx[j];
            s0 += xv * wm0[j];
            s1 += xv * wm1[j];
        }
        __half2 h; h.x = __float2half(tanhf(s0)); h.y = __float2half(tanhf(s1));
        *reinterpret_cast<__half2*>(&S[(size_t)CARNUM * BH + base]) = h;
    }
}

// ---------------- fp16 HMMA GEMM ------------------------------------------------
// C[M, 512] = epilogue( sum_pairs A@W^T ), A row-major [m][k], W [n][k]
// act: 0 = store raw fp16 (no bias)
//      1 = tanh(acc + bias), store
//      3 = relu(acc + bias) + fused W2 head-dot -> part (no C store)
//      4 = tanh(acc + Z + bias), store
__global__ void __launch_bounds__(256, 1)
gemm_hmma(const __half* __restrict__ A1, const __half* __restrict__ A2,
          const __half* __restrict__ B1, const __half* __restrict__ B2,
          const float* __restrict__ bias, const __half* __restrict__ Z,
          __half* __restrict__ C, int act, int npairs,
          const float* __restrict__ W2, float* __restrict__ part) {
    extern __shared__ char smc[];
    unsigned smraw = (unsigned)__cvta_generic_to_shared(smc);
    unsigned sm = (smraw + 1023u) & ~1023u;

    int tid  = threadIdx.x;
    int warp = tid >> 5;
    int lane = tid & 31;
    int wm = warp >> 2;
    int wn = warp & 3;
    int li  = lane & 7;
    int grp = lane >> 3;
    int mBase = blockIdx.y * BM;
    int nBase = blockIdx.x * BN;
    int NT = npairs * (HID / CHUNK_K);

    float acc[4][4][4];
#pragma unroll
    for (int mt = 0; mt < 4; ++mt)
#pragma unroll
        for (int nt = 0; nt < 4; ++nt)
#pragma unroll
            for (int c = 0; c < 4; ++c) acc[mt][nt][c] = 0.f;

    auto prefetch = [&](int chunk) {
        int buf = chunk % STAGES;
        int pair = chunk >> 3;
        int k0 = (chunk & 7) * CHUNK_K;
        const __half* PA = pair ? A2 : A1;
        const __half* PB = pair ? B2 : B1;
        unsigned sb = sm + buf * STAGE_BYTES;
#pragma unroll
        for (int i = 0; i < 8; ++i) {
            int cid = tid + 256 * i;
            int arr = cid >> 10;
            int r   = (cid >> 3) & 127;
            int seg = cid & 7;
            const __half* p = arr ? PB : PA;
            int rb = (arr ? nBase : mBase) + r;
            const void* src = p + (size_t)rb * HID + k0 + seg * 8;
            unsigned dst = sb + arr * TILE_BYTES + SW128(r * 128 + seg * 16);
            cp16(dst, src);
        }
        asm volatile("cp.async.commit_group;" ::: "memory");
    };

    prefetch(0);
    if (NT > 1) prefetch(1);

    for (int c = 0; c < NT; ++c) {
        if (c + 2 < NT) prefetch(c + 2);
        if (c + 2 < NT)      asm volatile("cp.async.wait_group 2;" ::: "memory");
        else if (c + 1 < NT) asm volatile("cp.async.wait_group 1;" ::: "memory");
        else                 asm volatile("cp.async.wait_group 0;" ::: "memory");
        __syncthreads();

        unsigned sb = sm + (c % STAGES) * STAGE_BYTES;
        unsigned sA = sb;
        unsigned sB = sb + TILE_BYTES;

#pragma unroll
        for (int kq = 0; kq < 4; ++kq) {
            unsigned a[4][4];
#pragma unroll
            for (int mt = 0; mt < 4; ++mt) {
                int r = wm * 64 + mt * 16 + ((grp & 1) << 3) + li;
                int cc = kq * 32 + ((grp & 2) << 3);
                unsigned off = (unsigned)(r * 128 + (cc ^ (li << 4)));
                ldsm4(a[mt], sA + off);
            }
            unsigned b[2][4];
#pragma unroll
            for (int nb = 0; nb < 2; ++nb) {
                int n = wn * 32 + nb * 16 + ((grp & 2) << 2) + li;
                int cc = kq * 32 + ((grp & 1) << 4);
                unsigned off = (unsigned)(n * 128 + (cc ^ (li << 4)));
                ldsm4(b[nb], sB + off);
            }
#pragma unroll
            for (int mt = 0; mt < 4; ++mt)
#pragma unroll
                for (int nt = 0; nt < 4; ++nt)
                    mma16816(acc[mt][nt], a[mt], &b[nt >> 1][(nt & 1) * 2]);
        }
        __syncthreads();
    }

    if (act != 3) {
#pragma unroll
        for (int mt = 0; mt < 4; ++mt) {
            int r0 = mBase + wm * 64 + mt * 16 + (lane >> 2);
#pragma unroll
            for (int nt = 0; nt < 4; ++nt) {
                int n0 = nBase + wn * 32 + nt * 8 + 2 * (lane & 3);
                float b0 = 0.f, b1 = 0.f;
                if (act != 0) { b0 = bias[n0]; b1 = bias[n0 + 1]; }
#pragma unroll
                for (int half_ = 0; half_ < 2; ++half_) {
                    int r = r0 + half_ * 8;
                    float v0 = acc[mt][nt][half_ * 2 + 0] + b0;
                    float v1 = acc[mt][nt][half_ * 2 + 1] + b1;
                    if (act == 4) {
                        __half2 z2 = *reinterpret_cast<const __half2*>(&Z[(size_t)r * HID + n0]);
                        v0 += __half2float(z2.x);
                        v1 += __half2float(z2.y);
                    }
                    if (act == 1 || act == 4) { v0 = tanhf(v0); v1 = tanhf(v1); }
                    __half2 hv; hv.x = __float2half(v0); hv.y = __float2half(v1);
                    *reinterpret_cast<__half2*>(&C[(size_t)r * HID + n0]) = hv;
                }
            }
        }
    } else {
        float p0[8], p1[8];
#pragma unroll
        for (int s2i = 0; s2i < 8; ++s2i) { p0[s2i] = 0.f; p1[s2i] = 0.f; }
#pragma unroll
        for (int nt = 0; nt < 4; ++nt) {
            int n0 = nBase + wn * 32 + nt * 8 + 2 * (lane & 3);
            float b0 = bias[n0], b1 = bias[n0 + 1];
            float w00 = W2[n0], w01 = W2[n0 + 1];
            float w10 = W2[HID + n0], w11 = W2[HID + n0 + 1];
#pragma unroll
            for (int mt = 0; mt < 4; ++mt)
#pragma unroll
                for (int half_ = 0; half_ < 2; ++half_) {
                    float v0 = fmaxf(acc[mt][nt][half_ * 2 + 0] + b0, 0.f);
                    float v1 = fmaxf(acc[mt][nt][half_ * 2 + 1] + b1, 0.f);
                    int s2i = mt * 2 + half_;
                    p0[s2i] += v0 * w00 + v1 * w01;
                    p1[s2i] += v0 * w10 + v1 * w11;
                }
        }
#pragma unroll
        for (int s2i = 0; s2i < 8; ++s2i) {
            p0[s2i] += __shfl_xor_sync(0xffffffffu, p0[s2i], 1);
            p0[s2i] += __shfl_xor_sync(0xffffffffu, p0[s2i], 2);
            p1[s2i] += __shfl_xor_sync(0xffffffffu, p1[s2i], 1);
            p1[s2i] += __shfl_xor_sync(0xffffffffu, p1[s2i], 2);
        }
        float* red = (float*)smc;
        if ((lane & 3) == 0) {
#pragma unroll
            for (int mt = 0; mt < 4; ++mt)
#pragma unroll
                for (int half_ = 0; half_ < 2; ++half_) {
                    int rl = wm * 64 + mt * 16 + (lane >> 2) + half_ * 8;
                    int s2i = mt * 2 + half_;
                    red[(rl * 2 + 0) * 4 + wn] = p0[s2i];
                    red[(rl * 2 + 1) * 4 + wn] = p1[s2i];
                }
        }
        __syncthreads();
        {
            float s = red[tid * 4 + 0] + red[tid * 4 + 1] + red[tid * 4 + 2] + red[tid * 4 + 3];
            part[((size_t)blockIdx.x * MHEAD + mBase + (tid >> 1)) * 2 + (tid & 1)] = s;
        }
    }
}

// out[b][t][o] = tanh(sum_4 part + b2[o]); row r = t*BATCH + b
__global__ void finalize_kernel(const float* __restrict__ part,
                                const float* __restrict__ b2, float* __restrict__ out) {
    int idx = blockIdx.x * blockDim.x + threadIdx.x;
    if (idx >= MHEAD * 2) return;
    int o = idx & 1;
    int r = idx >> 1;
    int b = r & (BATCH - 1);
    int t = r >> 12;
    float s = part[((size_t)0 * MHEAD + r) * 2 + o]
            + part[((size_t)1 * MHEAD + r) * 2 + o]
            + part[((size_t)2 * MHEAD + r) * 2 + o]
            + part[((size_t)3 * MHEAD + r) * 2 + o];
    out[((size_t)b * TDEC + t) * 2 + o] = tanhf(s + b2[o]);
}

// ---------------- static stream/event resources --------------------------------
static cudaStream_t g_s2 = nullptr;  // filler stream, LOW priority
static cudaEvent_t g_evEmb;
static cudaEvent_t g_evZ1[SEQLEN];   // Z1 part t ready (s2)
static cudaEvent_t g_evE[SEQLEN];    // enc l1 step t done (main)
static cudaEvent_t g_evZ2[SEQLEN];   // Z2 part t ready (s2)
static cudaEvent_t g_evD[TDEC];      // dec l2 step k done (main)
static cudaEvent_t g_evHead;         // all head parts done (s2)

static void ensure_resources() {
    if (g_s2) return;
    int lo, hi;
    cudaDeviceGetStreamPriorityRange(&lo, &hi);
    cudaStreamCreateWithPriority(&g_s2, cudaStreamNonBlocking, lo);  // LOW priority
    cudaEventCreateWithFlags(&g_evEmb, cudaEventDisableTiming);
    for (int i = 0; i < SEQLEN; ++i) {
        cudaEventCreateWithFlags(&g_evZ1[i], cudaEventDisableTiming);
        cudaEventCreateWithFlags(&g_evE[i],  cudaEventDisableTiming);
        cudaEventCreateWithFlags(&g_evZ2[i], cudaEventDisableTiming);
    }
    for (int i = 0; i < TDEC; ++i)
        cudaEventCreateWithFlags(&g_evD[i], cudaEventDisableTiming);
    cudaEventCreateWithFlags(&g_evHead, cudaEventDisableTiming);
}

// ---------------- launch ------------------------------------------------------
extern "C" void kernel_launch(void* const* d_in, const int* in_sizes, int n_in,
                              void* d_out, int out_size) {
    (void)in_sizes; (void)n_in; (void)out_size;
    const float* x      = (const float*)d_in[0];
    const float* emW    = (const float*)d_in[1];
    const float* emb    = (const float*)d_in[2];
    const float* evW    = (const float*)d_in[3];
    const float* evb    = (const float*)d_in[4];
    const float* encWih = (const float*)d_in[5];
    const float* encWhh = (const float*)d_in[6];
    const float* encbih = (const float*)d_in[7];
    const float* encbhh = (const float*)d_in[8];
    const float* decWih = (const float*)d_in[9];
    const float* decWhh = (const float*)d_in[10];
    const float* decbih = (const float*)d_in[11];
    const float* decbhh = (const float*)d_in[12];
    const float* headW1 = (const float*)d_in[13];
    const float* headb1 = (const float*)d_in[14];
    const float* headW2 = (const float*)d_in[15];
    const float* headb2 = (const float*)d_in[16];
    float* out = (float*)d_out;

    ensure_resources();

    __half *S, *Zb, *H1, *He, *Hd, *H2d, *W;
    float *bias, *part;
    cudaGetSymbolAddress((void**)&S,   g_S);
    cudaGetSymbolAddress((void**)&Zb,  g_Z);
    cudaGetSymbolAddress((void**)&H1,  g_H1);
    cudaGetSymbolAddress((void**)&He,  g_He);
    cudaGetSymbolAddress((void**)&Hd,  g_Hd);
    cudaGetSymbolAddress((void**)&H2d, g_H2d);
    cudaGetSymbolAddress((void**)&W,   g_W);
    cudaGetSymbolAddress((void**)&bias, g_bias);
    cudaGetSymbolAddress((void**)&part, g_part);

    cudaFuncSetAttribute(gemm_hmma, cudaFuncAttributeMaxDynamicSharedMemorySize, SMEM_REQ);

    Ptr9 src;
    src.p[0] = encWih;        src.p[1] = encWhh;
    src.p[2] = encWih + MM;   src.p[3] = encWhh + MM;
    src.p[4] = decWih;        src.p[5] = decWhh;
    src.p[6] = decWih + MM;   src.p[7] = decWhh + MM;
    src.p[8] = headW1;

    // prep, all on capture-origin stream 0 (capture-legal)
    wsplit_kernel<<<dim3(MM / 256, 9), 256>>>(src, W);
    bias_kernel<<<8, 256>>>(encbih, encbhh, decbih, decbhh, bias);
    zeroh_kernel<<<(BH + 255) / 256, 256>>>(H1, BH);
    embed_all_kernel<<<BATCH, 256>>>(x, emW, emb, evW, evb, S);
    cudaEventRecord(g_evEmb, 0);

    const __half* ZN = nullptr;
    const float* FN = nullptr;
    __half* CN = nullptr;
    dim3 gSerial(4, 32);

    // ===== s2 (low prio, forked from origin): Z1 parts 1..32 =====
    cudaStreamWaitEvent(g_s2, g_evEmb, 0);
    for (int t = 1; t < SEQLEN; ++t) {
        gemm_hmma<<<gSerial, 256, SMEM_REQ, g_s2>>>(
            S + (size_t)t * BH, ZN, W + 0 * MM, ZN, FN, ZN,
            Zb + (size_t)t * BH, 0, 1, FN, (float*)nullptr);
        cudaEventRecord(g_evZ1[t], g_s2);
    }

    // ===== main (origin stream): Z1 part 0, then serial l1 chain =====
    gemm_hmma<<<gSerial, 256, SMEM_REQ>>>(
        S, ZN, W + 0 * MM, ZN, FN, ZN, Zb, 0, 1, FN, (float*)nullptr);
    for (int t = 0; t < SEQLEN; ++t) {
        if (t >= 1) cudaStreamWaitEvent(0, g_evZ1[t], 0);
        gemm_hmma<<<gSerial, 256, SMEM_REQ>>>(
            H1 + (size_t)t * BH, ZN, W + 1 * MM, ZN,
            bias + 0 * HID, Zb + (size_t)t * BH,
            H1 + (size_t)(t + 1) * BH, 4, 1, FN, (float*)nullptr);
        cudaEventRecord(g_evE[t], 0);
    }

    // ===== s2: Z2 parts (each needs l1 step t done; overwrites Zb slot t) =====
    for (int t = 0; t < SEQLEN; ++t) {
        cudaStreamWaitEvent(g_s2, g_evE[t], 0);
        gemm_hmma<<<gSerial, 256, SMEM_REQ, g_s2>>>(
            H1 + (size_t)(t + 1) * BH, ZN, W + 2 * MM, ZN, FN, ZN,
            Zb + (size_t)t * BH, 0, 1, FN, (float*)nullptr);
        cudaEventRecord(g_evZ2[t], g_s2);
    }

    // ===== main: serial enc l2 chain =====
    for (int t = 0; t < SEQLEN; ++t) {
        cudaStreamWaitEvent(0, g_evZ2[t], 0);
        const __half* Aprev = (t == 0) ? H1 /*zeros*/ : He + (size_t)((t - 1) & 1) * BH;
        __half* dst = (t == SEQLEN - 1) ? H2d : He + (size_t)(t & 1) * BH;
        gemm_hmma<<<gSerial, 256, SMEM_REQ>>>(
            Aprev, ZN, W + 3 * MM, ZN,
            bias + 1 * HID, Zb + (size_t)t * BH,
            dst, 4, 1, FN, (float*)nullptr);
    }

    // ===== main: decoder; s2: per-k head parts overlapped =====
    for (int k = 0; k < TDEC; ++k) {
        const __half* h1prev = (k == 0) ? H1 + (size_t)SEQLEN * BH
                                        : Hd + (size_t)((k - 1) & 1) * BH;
        __half* h1cur = Hd + (size_t)(k & 1) * BH;
        gemm_hmma<<<gSerial, 256, SMEM_REQ>>>(
            H2d + (size_t)k * BH, h1prev, W + 4 * MM, W + 5 * MM,
            bias + 2 * HID, ZN, h1cur, 1, 2, FN, (float*)nullptr);
        gemm_hmma<<<gSerial, 256, SMEM_REQ>>>(
            h1cur, H2d + (size_t)k * BH, W + 6 * MM, W + 7 * MM,
            bias + 3 * HID, ZN, H2d + (size_t)(k + 1) * BH, 1, 2, FN, (float*)nullptr);
        cudaEventRecord(g_evD[k], 0);

        cudaStreamWaitEvent(g_s2, g_evD[k], 0);
        gemm_hmma<<<gSerial, 256, SMEM_REQ, g_s2>>>(
            H2d + (size_t)(k + 1) * BH, ZN, W + 8 * MM, ZN,
            headb1, ZN, CN, 3, 1, headW2,
            part + (size_t)k * BATCH * 2);
    }
    cudaEventRecord(g_evHead, g_s2);

    // ===== join + finalize =====
    cudaStreamWaitEvent(0, g_evHead, 0);
    finalize_kernel<<<(MHEAD * 2 + 255) / 256, 256>>>(part, headb2, out);
}